// round 1
// baseline (speedup 1.0000x reference)
#include <cuda_runtime.h>
#include <cstdint>

// ---------------- problem constants ----------------
#define B_    4
#define L_    2048
#define DM    1024          // d_model
#define DI    2048          // d_inner
#define DS    16            // d_state
#define DR    64            // dt_rank
#define XZW   (2*DI)        // 4096  width of xz
#define DBLW  (DR + 2*DS)   // 96    width of dbl
#define ML    (B_*L_)       // 8192  rows of all GEMMs

// ---------------- scratch (static device globals; allocation-free) ----------
__device__ float g_xz   [(size_t)ML * XZW];   // 128 MiB
__device__ float g_xconv[(size_t)ML * DI];    //  64 MiB
__device__ float g_dbl  [(size_t)ML * DBLW];  //   3 MiB
__device__ float g_dt   [(size_t)ML * DI];    //  64 MiB
__device__ float g_y    [(size_t)ML * DI];    //  64 MiB

// ---------------- helpers ----------------
__device__ __forceinline__ float softplusf(float x) {
    return x > 20.f ? x : log1pf(__expf(x));
}
__device__ __forceinline__ float siluf(float x) {
    return x / (1.f + __expf(-x));
}

// ---------------- generic NT SGEMM: C[M,N] = A[M,K] * B[N,K]^T ------------
// A row-major (lda), B row-major (ldb), C row-major (ldc).
// EPI: 0 = none, 1 = softplus(acc + bias[n])
template<int BM, int BN, int BK, int TM, int TN, int EPI>
__global__ void sgemm_nt(int M, int N, int K,
                         const float* __restrict__ A, int lda,
                         const float* __restrict__ Bm, int ldb,
                         float* __restrict__ C, int ldc,
                         const float* __restrict__ bias)
{
    constexpr int THREADS = (BM/TM) * (BN/TN);
    constexpr int KV = BK / 4;          // float4 per row of a tile
    constexpr int AV = BM * KV;         // float4 loads for A tile
    constexpr int BV = BN * KV;         // float4 loads for B tile

    __shared__ float As[BK][BM];
    __shared__ float Bs[BK][BN];

    const int tid = threadIdx.x;
    const int tx  = tid % (BN/TN);
    const int ty  = tid / (BN/TN);
    const int bm  = blockIdx.y * BM;
    const int bn  = blockIdx.x * BN;

    float acc[TM][TN];
    #pragma unroll
    for (int i = 0; i < TM; i++)
        #pragma unroll
        for (int j = 0; j < TN; j++) acc[i][j] = 0.f;

    for (int k0 = 0; k0 < K; k0 += BK) {
        // load A tile (transposed into As[k][m])
        for (int i = tid; i < AV; i += THREADS) {
            int row = i / KV, kq = i % KV;
            float4 v = *(const float4*)&A[(size_t)(bm + row) * lda + k0 + kq*4];
            As[kq*4+0][row] = v.x; As[kq*4+1][row] = v.y;
            As[kq*4+2][row] = v.z; As[kq*4+3][row] = v.w;
        }
        // load B tile (transposed into Bs[k][n]) with N guard
        for (int i = tid; i < BV; i += THREADS) {
            int row = i / KV, kq = i % KV;
            float4 v = make_float4(0.f, 0.f, 0.f, 0.f);
            if (bn + row < N)
                v = *(const float4*)&Bm[(size_t)(bn + row) * ldb + k0 + kq*4];
            Bs[kq*4+0][row] = v.x; Bs[kq*4+1][row] = v.y;
            Bs[kq*4+2][row] = v.z; Bs[kq*4+3][row] = v.w;
        }
        __syncthreads();

        #pragma unroll
        for (int k = 0; k < BK; k++) {
            float ar[TM], br[TN];
            #pragma unroll
            for (int i = 0; i < TM; i++) ar[i] = As[k][ty*TM + i];
            #pragma unroll
            for (int j = 0; j < TN; j++) br[j] = Bs[k][tx*TN + j];
            #pragma unroll
            for (int i = 0; i < TM; i++)
                #pragma unroll
                for (int j = 0; j < TN; j++)
                    acc[i][j] = fmaf(ar[i], br[j], acc[i][j]);
        }
        __syncthreads();
    }

    #pragma unroll
    for (int i = 0; i < TM; i++) {
        int m = bm + ty*TM + i;
        if (m >= M) continue;
        #pragma unroll
        for (int j = 0; j < TN; j++) {
            int n = bn + tx*TN + j;
            if (n >= N) continue;
            float v = acc[i][j];
            if (EPI == 1) v = softplusf(v + bias[n]);
            C[(size_t)m * ldc + n] = v;
        }
    }
}

// ---------------- depthwise causal conv (K=4) + silu ----------------
// x_in = g_xz[..., :DI]; out -> g_xconv
#define TC 128
__global__ void conv_silu_kernel(const float* __restrict__ conv_w)
{
    const int d  = blockIdx.x * blockDim.x + threadIdx.x;   // 0..DI-1
    const int t0 = blockIdx.y * TC;
    const int b  = blockIdx.z;

    const float w0 = conv_w[d*4+0], w1 = conv_w[d*4+1],
                w2 = conv_w[d*4+2], w3 = conv_w[d*4+3];

    const float* xin = g_xz + (size_t)b * L_ * XZW + d;     // stride XZW in t
    float*       out = g_xconv + (size_t)b * L_ * DI + d;   // stride DI in t

    float x0 = (t0-3 >= 0) ? xin[(size_t)(t0-3)*XZW] : 0.f;
    float x1 = (t0-2 >= 0) ? xin[(size_t)(t0-2)*XZW] : 0.f;
    float x2 = (t0-1 >= 0) ? xin[(size_t)(t0-1)*XZW] : 0.f;

    for (int t = t0; t < t0 + TC; t++) {
        float x3 = xin[(size_t)t * XZW];
        float s  = fmaf(x0, w0, fmaf(x1, w1, fmaf(x2, w2, x3*w3)));
        out[(size_t)t * DI] = siluf(s);
        x0 = x1; x1 = x2; x2 = x3;
    }
}

// ---------------- selective scan, fused with Dp skip + silu(z) gate -------
// one lane per (channel, state): warp = 2 channels x 16 states.
// y[b,t,d] = (sum_n h*C + Dp[d]*x_conv) * silu(z)
__global__ void scan_kernel(const float* __restrict__ A_log,
                            const float* __restrict__ Dp)
{
    const int gw   = (blockIdx.x * blockDim.x + threadIdx.x) >> 5; // warp id
    const int lane = threadIdx.x & 31;
    const int b    = gw >> 10;            // 1024 warps per batch
    const int d    = ((gw & 1023) << 1) + (lane >> 4);
    const int n    = lane & 15;

    const float a  = -__expf(A_log[d*DS + n]);
    const float Dd = Dp[d];

    const float* dtr  = g_dt    + (size_t)b * L_ * DI + d;
    const float* xcr  = g_xconv + (size_t)b * L_ * DI + d;
    const float* dbb  = g_dbl   + (size_t)b * L_ * DBLW;
    const float* zr   = g_xz    + (size_t)b * L_ * XZW + DI + d;
    float*       yr   = g_y     + (size_t)b * L_ * DI + d;

    float h = 0.f;
    for (int t = 0; t < L_; t++) {
        const float dt = dtr[(size_t)t * DI];
        const float xv = xcr[(size_t)t * DI];
        const float Bn = dbb[(size_t)t * DBLW + DR + n];
        const float Cn = dbb[(size_t)t * DBLW + DR + DS + n];

        const float da = __expf(dt * a);
        h = fmaf(h, da, dt * Bn * xv);

        float p = h * Cn;
        p += __shfl_xor_sync(0xffffffffu, p, 1);
        p += __shfl_xor_sync(0xffffffffu, p, 2);
        p += __shfl_xor_sync(0xffffffffu, p, 4);
        p += __shfl_xor_sync(0xffffffffu, p, 8);

        if (n == 0) {
            const float zv = zr[(size_t)t * XZW];
            yr[(size_t)t * DI] = (p + Dd * xv) * siluf(zv);
        }
    }
}

// ---------------- launch ----------------
extern "C" void kernel_launch(void* const* d_in, const int* in_sizes, int n_in,
                              void* d_out, int out_size)
{
    const float* x      = (const float*)d_in[0];
    const float* W_in   = (const float*)d_in[1];
    const float* conv_w = (const float*)d_in[2];
    const float* W_x    = (const float*)d_in[3];
    const float* W_dt   = (const float*)d_in[4];
    const float* b_dt   = (const float*)d_in[5];
    const float* A_log  = (const float*)d_in[6];
    const float* Dp     = (const float*)d_in[7];
    const float* W_out  = (const float*)d_in[8];
    float* out = (float*)d_out;

    float *xz, *xconv, *dbl, *dt, *y;
    cudaGetSymbolAddress((void**)&xz,    g_xz);
    cudaGetSymbolAddress((void**)&xconv, g_xconv);
    cudaGetSymbolAddress((void**)&dbl,   g_dbl);
    cudaGetSymbolAddress((void**)&dt,    g_dt);
    cudaGetSymbolAddress((void**)&y,     g_y);

    // 1) xz = x @ W_in^T    (8192 x 4096 x K=1024)
    {
        dim3 grid(XZW/128, ML/128);
        sgemm_nt<128,128,16,8,8,0><<<grid, 256>>>(ML, XZW, DM, x, DM, W_in, DM, xz, XZW, nullptr);
    }
    // 2) depthwise conv + silu
    {
        dim3 grid(DI/256, L_/TC, B_);
        conv_silu_kernel<<<grid, 256>>>(conv_w);
    }
    // 3) dbl = x_conv @ W_x^T   (8192 x 96 x K=2048) — skinny N, small tiles
    {
        dim3 grid((DBLW + 31)/32, ML/64);
        sgemm_nt<64,32,16,4,4,0><<<grid, 128>>>(ML, DBLW, DI, xconv, DI, W_x, DI, dbl, DBLW, nullptr);
    }
    // 4) dt = softplus(dbl[:, :64] @ W_dt^T + b_dt)   (8192 x 2048 x K=64)
    {
        dim3 grid(DI/128, ML/128);
        sgemm_nt<128,128,16,8,8,1><<<grid, 256>>>(ML, DI, DR, dbl, DBLW, W_dt, DR, dt, DI, b_dt);
    }
    // 5) selective scan (fused skip + gate) : 4096 warps
    {
        int warps = B_ * (DI/2);
        scan_kernel<<<warps*32/256, 256>>>(A_log, Dp);
    }
    // 6) out = y @ W_out^T   (8192 x 1024 x K=2048)
    {
        dim3 grid(DM/128, ML/128);
        sgemm_nt<128,128,16,8,8,0><<<grid, 256>>>(ML, DM, DI, y, DI, W_out, DI, out, DM, nullptr);
    }
}

// round 2
// speedup vs baseline: 1.6442x; 1.6442x over previous
#include <cuda_runtime.h>
#include <cstdint>

// ---------------- problem constants ----------------
#define B_    4
#define L_    2048
#define DM    1024          // d_model
#define DI    2048          // d_inner
#define DS    16            // d_state
#define DR    64            // dt_rank
#define XZW   (2*DI)        // 4096  width of xz
#define DBLW  (DR + 2*DS)   // 96    width of dbl
#define ML    (B_*L_)       // 8192  rows of all GEMMs

// ---------------- scratch (static device globals; allocation-free) ----------
__device__ float g_xz   [(size_t)ML * XZW];   // 128 MiB
__device__ float g_xconv[(size_t)ML * DI];    //  64 MiB
__device__ float g_dbl  [(size_t)ML * DBLW];  //   3 MiB
__device__ float g_dt   [(size_t)ML * DI];    //  64 MiB
__device__ float g_y    [(size_t)ML * DI];    //  64 MiB

// ---------------- helpers ----------------
__device__ __forceinline__ float softplusf(float x) {
    return x > 20.f ? x : log1pf(__expf(x));
}
__device__ __forceinline__ float siluf(float x) {
    return x / (1.f + __expf(-x));
}
__device__ __forceinline__ uint32_t f2tf(float f) {
    uint32_t u;
    asm("cvt.rna.tf32.f32 %0, %1;" : "=r"(u) : "f"(f));
    return u;
}
__device__ __forceinline__ uint32_t s2u(const void* p) {
    return (uint32_t)__cvta_generic_to_shared(p);
}

#define LDSM4(R, addr) \
    asm volatile("ldmatrix.sync.aligned.m8n8.x4.shared.b16 {%0,%1,%2,%3}, [%4];" \
        : "=r"((R)[0]), "=r"((R)[1]), "=r"((R)[2]), "=r"((R)[3]) : "r"(addr))

#define MMA_TF32(C, A, B0, B1) \
    asm volatile("mma.sync.aligned.m16n8k8.row.col.f32.tf32.tf32.f32 " \
        "{%0,%1,%2,%3}, {%4,%5,%6,%7}, {%8,%9}, {%0,%1,%2,%3};" \
        : "+f"((C)[0]), "+f"((C)[1]), "+f"((C)[2]), "+f"((C)[3]) \
        : "r"((A)[0]), "r"((A)[1]), "r"((A)[2]), "r"((A)[3]), "r"(B0), "r"(B1))

// ---------------- tf32 tensor-core NT GEMM: C[M,N] = A[M,K] * B[N,K]^T ----
// BM=BN=128, BK=16, 256 threads, warp tile 64x32 (m16n8k8 mma).
// Requires M%128==0, N%128==0, K%16==0, lda/ldb multiples of 4.
// smem layout: row-major [row][16 floats], float4 units XOR-swizzled:
//   unit(row,kq) = 4*row + (kq ^ ((row>>1)&3))  -> conflict-free STS.128 and ldmatrix.
__global__ __launch_bounds__(256, 2)
void mma_nt_tf32(int M, int N, int K,
                 const float* __restrict__ A, int lda,
                 const float* __restrict__ Bm, int ldb,
                 float* __restrict__ C, int ldc)
{
    __shared__ float As[128 * 16];
    __shared__ float Bs[128 * 16];

    const int tid  = threadIdx.x;
    const int lane = tid & 31;
    const int wid  = tid >> 5;
    const int wm   = wid & 1;        // 2 warps along M
    const int wn   = wid >> 1;       // 4 warps along N
    const int bm   = blockIdx.y * 128;
    const int bn   = blockIdx.x * 128;

    const uint32_t as_base = s2u(As);
    const uint32_t bs_base = s2u(Bs);

    // --- global load mapping: thread -> (row = tid/4 [+64], kq = tid%4) ---
    const int lrow = tid >> 2;
    const int lkq  = tid & 3;
    const float* pa = A  + (size_t)(bm + lrow) * lda + lkq * 4;
    const float* pb = Bm + (size_t)(bn + lrow) * ldb + lkq * 4;
    const size_t a64 = (size_t)64 * lda;
    const size_t b64 = (size_t)64 * ldb;

    // --- smem store addresses (swizzled), fixed across iterations ---
    #define SWZ(row, kq) ((((row) << 2) + ((kq) ^ (((row) >> 1) & 3))) * 16)
    const uint32_t stA0 = as_base + SWZ(lrow,      lkq);
    const uint32_t stA1 = as_base + SWZ(lrow + 64, lkq);
    const uint32_t stB0 = bs_base + SWZ(lrow,      lkq);
    const uint32_t stB1 = bs_base + SWZ(lrow + 64, lkq);

    // --- ldmatrix addresses ---
    const int r = lane & 7;
    const int j = lane >> 3;
    uint32_t a_addr[4][2];   // [mtile][kstep]
    #pragma unroll
    for (int mt = 0; mt < 4; mt++)
        #pragma unroll
        for (int ks = 0; ks < 2; ks++) {
            int row  = wm * 64 + mt * 16 + (j & 1) * 8 + r;
            int unit = ks * 2 + (j >> 1);
            a_addr[mt][ks] = as_base + SWZ(row, unit);
        }
    uint32_t b_addr[2][2];   // [octet-pair][kstep]
    #pragma unroll
    for (int pr = 0; pr < 2; pr++)
        #pragma unroll
        for (int ks = 0; ks < 2; ks++) {
            int row  = wn * 32 + pr * 16 + (j >> 1) * 8 + r;
            int unit = ks * 2 + (j & 1);
            b_addr[pr][ks] = bs_base + SWZ(row, unit);
        }

    float c[4][4][4];
    #pragma unroll
    for (int mt = 0; mt < 4; mt++)
        #pragma unroll
        for (int nt = 0; nt < 4; nt++)
            #pragma unroll
            for (int q = 0; q < 4; q++) c[mt][nt][q] = 0.f;

    // --- prologue: load tile 0 into registers ---
    float4 ra0 = *(const float4*)(pa);
    float4 ra1 = *(const float4*)(pa + a64);
    float4 rb0 = *(const float4*)(pb);
    float4 rb1 = *(const float4*)(pb + b64);

    const int niter = K >> 4;
    for (int it = 0; it < niter; ++it) {
        if (it) __syncthreads();     // smem free from previous compute

        // stage regs -> smem with tf32 RN rounding
        {
            uint4 u;
            u.x = f2tf(ra0.x); u.y = f2tf(ra0.y); u.z = f2tf(ra0.z); u.w = f2tf(ra0.w);
            asm volatile("st.shared.v4.b32 [%0], {%1,%2,%3,%4};" :: "r"(stA0), "r"(u.x), "r"(u.y), "r"(u.z), "r"(u.w));
            u.x = f2tf(ra1.x); u.y = f2tf(ra1.y); u.z = f2tf(ra1.z); u.w = f2tf(ra1.w);
            asm volatile("st.shared.v4.b32 [%0], {%1,%2,%3,%4};" :: "r"(stA1), "r"(u.x), "r"(u.y), "r"(u.z), "r"(u.w));
            u.x = f2tf(rb0.x); u.y = f2tf(rb0.y); u.z = f2tf(rb0.z); u.w = f2tf(rb0.w);
            asm volatile("st.shared.v4.b32 [%0], {%1,%2,%3,%4};" :: "r"(stB0), "r"(u.x), "r"(u.y), "r"(u.z), "r"(u.w));
            u.x = f2tf(rb1.x); u.y = f2tf(rb1.y); u.z = f2tf(rb1.z); u.w = f2tf(rb1.w);
            asm volatile("st.shared.v4.b32 [%0], {%1,%2,%3,%4};" :: "r"(stB1), "r"(u.x), "r"(u.y), "r"(u.z), "r"(u.w));
        }
        __syncthreads();

        // prefetch next tile (overlaps with mma below)
        if (it + 1 < niter) {
            const float* qa = pa + (size_t)(it + 1) * 16;
            const float* qb = pb + (size_t)(it + 1) * 16;
            ra0 = *(const float4*)(qa);
            ra1 = *(const float4*)(qa + a64);
            rb0 = *(const float4*)(qb);
            rb1 = *(const float4*)(qb + b64);
        }

        // compute 2 k-steps of m16n8k8
        #pragma unroll
        for (int ks = 0; ks < 2; ks++) {
            uint32_t bf[2][4];
            LDSM4(bf[0], b_addr[0][ks]);
            LDSM4(bf[1], b_addr[1][ks]);
            uint32_t af[4][4];
            #pragma unroll
            for (int mt = 0; mt < 4; mt++) LDSM4(af[mt], a_addr[mt][ks]);
            #pragma unroll
            for (int mt = 0; mt < 4; mt++)
                #pragma unroll
                for (int nt = 0; nt < 4; nt++)
                    MMA_TF32(c[mt][nt], af[mt],
                             bf[nt >> 1][(nt & 1) * 2], bf[nt >> 1][(nt & 1) * 2 + 1]);
        }
    }

    // --- epilogue ---
    #pragma unroll
    for (int mt = 0; mt < 4; mt++) {
        #pragma unroll
        for (int nt = 0; nt < 4; nt++) {
            int m0 = bm + wm * 64 + mt * 16 + (lane >> 2);
            int n0 = bn + wn * 32 + nt * 8 + (lane & 3) * 2;
            *(float2*)&C[(size_t)m0 * ldc + n0]       = make_float2(c[mt][nt][0], c[mt][nt][1]);
            *(float2*)&C[(size_t)(m0 + 8) * ldc + n0] = make_float2(c[mt][nt][2], c[mt][nt][3]);
        }
    }
    #undef SWZ
}

// ---------------- generic NT SGEMM (FFMA): C[M,N] = A[M,K] * B[N,K]^T ------
// EPI: 0 = none, 1 = softplus(acc + bias[n])
template<int BM, int BN, int BK, int TM, int TN, int EPI>
__global__ void sgemm_nt(int M, int N, int K,
                         const float* __restrict__ A, int lda,
                         const float* __restrict__ Bm, int ldb,
                         float* __restrict__ C, int ldc,
                         const float* __restrict__ bias)
{
    constexpr int THREADS = (BM/TM) * (BN/TN);
    constexpr int KV = BK / 4;
    constexpr int AV = BM * KV;
    constexpr int BV = BN * KV;

    __shared__ float As[BK][BM];
    __shared__ float Bs[BK][BN];

    const int tid = threadIdx.x;
    const int tx  = tid % (BN/TN);
    const int ty  = tid / (BN/TN);
    const int bm  = blockIdx.y * BM;
    const int bn  = blockIdx.x * BN;

    float acc[TM][TN];
    #pragma unroll
    for (int i = 0; i < TM; i++)
        #pragma unroll
        for (int j = 0; j < TN; j++) acc[i][j] = 0.f;

    for (int k0 = 0; k0 < K; k0 += BK) {
        for (int i = tid; i < AV; i += THREADS) {
            int row = i / KV, kq = i % KV;
            float4 v = *(const float4*)&A[(size_t)(bm + row) * lda + k0 + kq*4];
            As[kq*4+0][row] = v.x; As[kq*4+1][row] = v.y;
            As[kq*4+2][row] = v.z; As[kq*4+3][row] = v.w;
        }
        for (int i = tid; i < BV; i += THREADS) {
            int row = i / KV, kq = i % KV;
            float4 v = make_float4(0.f, 0.f, 0.f, 0.f);
            if (bn + row < N)
                v = *(const float4*)&Bm[(size_t)(bn + row) * ldb + k0 + kq*4];
            Bs[kq*4+0][row] = v.x; Bs[kq*4+1][row] = v.y;
            Bs[kq*4+2][row] = v.z; Bs[kq*4+3][row] = v.w;
        }
        __syncthreads();

        #pragma unroll
        for (int k = 0; k < BK; k++) {
            float ar[TM], br[TN];
            #pragma unroll
            for (int i = 0; i < TM; i++) ar[i] = As[k][ty*TM + i];
            #pragma unroll
            for (int j = 0; j < TN; j++) br[j] = Bs[k][tx*TN + j];
            #pragma unroll
            for (int i = 0; i < TM; i++)
                #pragma unroll
                for (int j = 0; j < TN; j++)
                    acc[i][j] = fmaf(ar[i], br[j], acc[i][j]);
        }
        __syncthreads();
    }

    #pragma unroll
    for (int i = 0; i < TM; i++) {
        int m = bm + ty*TM + i;
        if (m >= M) continue;
        #pragma unroll
        for (int j = 0; j < TN; j++) {
            int n = bn + tx*TN + j;
            if (n >= N) continue;
            float v = acc[i][j];
            if (EPI == 1) v = softplusf(v + bias[n]);
            C[(size_t)m * ldc + n] = v;
        }
    }
}

// ---------------- depthwise causal conv (K=4) + silu ----------------
#define TC 128
__global__ void conv_silu_kernel(const float* __restrict__ conv_w)
{
    const int d  = blockIdx.x * blockDim.x + threadIdx.x;
    const int t0 = blockIdx.y * TC;
    const int b  = blockIdx.z;

    const float w0 = conv_w[d*4+0], w1 = conv_w[d*4+1],
                w2 = conv_w[d*4+2], w3 = conv_w[d*4+3];

    const float* xin = g_xz + (size_t)b * L_ * XZW + d;
    float*       out = g_xconv + (size_t)b * L_ * DI + d;

    float x0 = (t0-3 >= 0) ? xin[(size_t)(t0-3)*XZW] : 0.f;
    float x1 = (t0-2 >= 0) ? xin[(size_t)(t0-2)*XZW] : 0.f;
    float x2 = (t0-1 >= 0) ? xin[(size_t)(t0-1)*XZW] : 0.f;

    for (int t = t0; t < t0 + TC; t++) {
        float x3 = xin[(size_t)t * XZW];
        float s  = fmaf(x0, w0, fmaf(x1, w1, fmaf(x2, w2, x3*w3)));
        out[(size_t)t * DI] = siluf(s);
        x0 = x1; x1 = x2; x2 = x3;
    }
}

// ---------------- selective scan, fused with Dp skip + silu(z) gate -------
__global__ void scan_kernel(const float* __restrict__ A_log,
                            const float* __restrict__ Dp)
{
    const int gw   = (blockIdx.x * blockDim.x + threadIdx.x) >> 5;
    const int lane = threadIdx.x & 31;
    const int b    = gw >> 10;
    const int d    = ((gw & 1023) << 1) + (lane >> 4);
    const int n    = lane & 15;

    const float a  = -__expf(A_log[d*DS + n]);
    const float Dd = Dp[d];

    const float* dtr  = g_dt    + (size_t)b * L_ * DI + d;
    const float* xcr  = g_xconv + (size_t)b * L_ * DI + d;
    const float* dbb  = g_dbl   + (size_t)b * L_ * DBLW;
    const float* zr   = g_xz    + (size_t)b * L_ * XZW + DI + d;
    float*       yr   = g_y     + (size_t)b * L_ * DI + d;

    float h = 0.f;
    for (int t = 0; t < L_; t++) {
        const float dt = dtr[(size_t)t * DI];
        const float xv = xcr[(size_t)t * DI];
        const float Bn = dbb[(size_t)t * DBLW + DR + n];
        const float Cn = dbb[(size_t)t * DBLW + DR + DS + n];

        const float da = __expf(dt * a);
        h = fmaf(h, da, dt * Bn * xv);

        float p = h * Cn;
        p += __shfl_xor_sync(0xffffffffu, p, 1);
        p += __shfl_xor_sync(0xffffffffu, p, 2);
        p += __shfl_xor_sync(0xffffffffu, p, 4);
        p += __shfl_xor_sync(0xffffffffu, p, 8);

        if (n == 0) {
            const float zv = zr[(size_t)t * XZW];
            yr[(size_t)t * DI] = (p + Dd * xv) * siluf(zv);
        }
    }
}

// ---------------- launch ----------------
extern "C" void kernel_launch(void* const* d_in, const int* in_sizes, int n_in,
                              void* d_out, int out_size)
{
    const float* x      = (const float*)d_in[0];
    const float* W_in   = (const float*)d_in[1];
    const float* conv_w = (const float*)d_in[2];
    const float* W_x    = (const float*)d_in[3];
    const float* W_dt   = (const float*)d_in[4];
    const float* b_dt   = (const float*)d_in[5];
    const float* A_log  = (const float*)d_in[6];
    const float* Dp     = (const float*)d_in[7];
    const float* W_out  = (const float*)d_in[8];
    float* out = (float*)d_out;

    float *xz, *xconv, *dbl, *dt, *y;
    cudaGetSymbolAddress((void**)&xz,    g_xz);
    cudaGetSymbolAddress((void**)&xconv, g_xconv);
    cudaGetSymbolAddress((void**)&dbl,   g_dbl);
    cudaGetSymbolAddress((void**)&dt,    g_dt);
    cudaGetSymbolAddress((void**)&y,     g_y);

    // 1) xz = x @ W_in^T    (8192 x 4096 x 1024) — tf32 tensor cores
    {
        dim3 grid(XZW/128, ML/128);
        mma_nt_tf32<<<grid, 256>>>(ML, XZW, DM, x, DM, W_in, DM, xz, XZW);
    }
    // 2) depthwise conv + silu
    {
        dim3 grid(DI/256, L_/TC, B_);
        conv_silu_kernel<<<grid, 256>>>(conv_w);
    }
    // 3) dbl = x_conv @ W_x^T   (8192 x 96 x 2048) — FFMA (exact, feeds scan)
    {
        dim3 grid((DBLW + 31)/32, ML/64);
        sgemm_nt<64,32,16,4,4,0><<<grid, 128>>>(ML, DBLW, DI, xconv, DI, W_x, DI, dbl, DBLW, nullptr);
    }
    // 4) dt = softplus(dbl[:, :64] @ W_dt^T + b_dt)   (8192 x 2048 x 64) — FFMA
    {
        dim3 grid(DI/128, ML/128);
        sgemm_nt<128,128,16,8,8,1><<<grid, 256>>>(ML, DI, DR, dbl, DBLW, W_dt, DR, dt, DI, b_dt);
    }
    // 5) selective scan (fused skip + gate)
    {
        int warps = B_ * (DI/2);
        scan_kernel<<<warps*32/256, 256>>>(A_log, Dp);
    }
    // 6) out = y @ W_out^T   (8192 x 1024 x 2048) — tf32 tensor cores
    {
        dim3 grid(DM/128, ML/128);
        mma_nt_tf32<<<grid, 256>>>(ML, DM, DI, y, DI, W_out, DI, out, DM);
    }
}

// round 3
// speedup vs baseline: 1.8318x; 1.1141x over previous
#include <cuda_runtime.h>
#include <cstdint>

// ---------------- problem constants ----------------
#define B_    4
#define L_    2048
#define DM    1024          // d_model
#define DI    2048          // d_inner
#define DS    16            // d_state
#define DR    64            // dt_rank
#define XZW   (2*DI)        // 4096  width of xz
#define DBLW  (DR + 2*DS)   // 96    width of dbl
#define ML    (B_*L_)       // 8192  rows of all GEMMs

// ---------------- scratch (static device globals; allocation-free) ----------
__device__ float g_xz   [(size_t)ML * XZW];   // 128 MiB
__device__ float g_xconv[(size_t)ML * DI];    //  64 MiB
__device__ float g_dbl  [(size_t)ML * DBLW];  //   3 MiB
__device__ float g_dt   [(size_t)ML * DI];    //  64 MiB
__device__ float g_y    [(size_t)ML * DI];    //  64 MiB
// tf32-rounded copies of inputs
__device__ float g_xr   [(size_t)ML * DM];    //  32 MiB
__device__ float g_win  [(size_t)XZW * DM];   //  16 MiB
__device__ float g_wx   [(size_t)DBLW * DI];  // 768 KiB
__device__ float g_wdt  [(size_t)DI * DR];    // 512 KiB
__device__ float g_wout [(size_t)DM * DI];    //   8 MiB

// ---------------- helpers ----------------
__device__ __forceinline__ float softplusf(float x) {
    return x > 20.f ? x : log1pf(__expf(x));
}
__device__ __forceinline__ float siluf(float x) {
    return x / (1.f + __expf(-x));
}
__device__ __forceinline__ uint32_t f2tf(float f) {
    uint32_t u;
    asm("cvt.rna.tf32.f32 %0, %1;" : "=r"(u) : "f"(f));
    return u;
}
__device__ __forceinline__ float roundtf(float f) {
    return __uint_as_float(f2tf(f));
}
__device__ __forceinline__ uint32_t s2u(const void* p) {
    return (uint32_t)__cvta_generic_to_shared(p);
}

#define LDSM4(R, addr) \
    asm volatile("ldmatrix.sync.aligned.m8n8.x4.shared.b16 {%0,%1,%2,%3}, [%4];" \
        : "=r"((R)[0]), "=r"((R)[1]), "=r"((R)[2]), "=r"((R)[3]) : "r"(addr))

#define MMA_TF32(C, A, B0, B1) \
    asm volatile("mma.sync.aligned.m16n8k8.row.col.f32.tf32.tf32.f32 " \
        "{%0,%1,%2,%3}, {%4,%5,%6,%7}, {%8,%9}, {%0,%1,%2,%3};" \
        : "+f"((C)[0]), "+f"((C)[1]), "+f"((C)[2]), "+f"((C)[3]) \
        : "r"((A)[0]), "r"((A)[1]), "r"((A)[2]), "r"((A)[3]), "r"(B0), "r"(B1))

#define CP16(dst, src, sz) \
    asm volatile("cp.async.cg.shared.global [%0], [%1], 16, %2;" \
        :: "r"(dst), "l"(src), "r"(sz))

// smem unit swizzle: byte offset of float4 unit (row, kq)
#define SWZ(row, kq) ((((row) << 2) + ((kq) ^ (((row) >> 1) & 3))) * 16)

// ---------------- tf32 tensor-core NT GEMM, 3-stage cp.async pipeline -----
// C[M,N] = A[M,K] * B[N,K]^T.  BM=BN=128, BK=16, 256 threads, warp tile 64x32.
// Inputs must be pre-rounded to tf32 (RN); kernel consumes raw bits.
// Requires M%128==0, K%16==0, lda/ldb multiples of 4. N guarded (loads+stores).
// EPI: 0=none, 1=softplus(v+bias[n]), 2=round output to tf32.
template<int EPI>
__global__ __launch_bounds__(256, 2)
void mma_nt_tf32(int M, int N, int K,
                 const float* __restrict__ A, int lda,
                 const float* __restrict__ Bm, int ldb,
                 float* __restrict__ C, int ldc,
                 const float* __restrict__ bias)
{
    constexpr int STAGES = 3;
    constexpr int STAGE_BYTES = 128 * 16 * 4;
    __shared__ float As[STAGES][128 * 16];
    __shared__ float Bs[STAGES][128 * 16];

    const int tid  = threadIdx.x;
    const int lane = tid & 31;
    const int wid  = tid >> 5;
    const int wm   = wid & 1;
    const int wn   = wid >> 1;
    const int bm   = blockIdx.y * 128;
    const int bn   = blockIdx.x * 128;

    const uint32_t as_base = s2u(As);
    const uint32_t bs_base = s2u(Bs);

    // global load mapping: thread -> (row = tid/4 [+64], kq = tid%4)
    const int lrow = tid >> 2;
    const int lkq  = tid & 3;
    const float* pa = A + (size_t)(bm + lrow) * lda + lkq * 4;
    const size_t a64 = (size_t)64 * lda;
    const int brow0 = bn + lrow, brow1 = bn + lrow + 64;
    const uint32_t bsz0 = (brow0 < N) ? 16u : 0u;
    const uint32_t bsz1 = (brow1 < N) ? 16u : 0u;
    const float* pb0 = Bm + (size_t)(brow0 < N ? brow0 : N - 1) * ldb + lkq * 4;
    const float* pb1 = Bm + (size_t)(brow1 < N ? brow1 : N - 1) * ldb + lkq * 4;

    // smem store byte offsets (within a stage)
    const uint32_t offA0 = SWZ(lrow, lkq);
    const uint32_t offA1 = SWZ(lrow + 64, lkq);
    const uint32_t offB0 = offA0;           // same (row,kq) mapping for B
    const uint32_t offB1 = offA1;

    // ldmatrix byte offsets (within a stage)
    const int r = lane & 7;
    const int j = lane >> 3;
    uint32_t a_off[4][2];
    #pragma unroll
    for (int mt = 0; mt < 4; mt++)
        #pragma unroll
        for (int ks = 0; ks < 2; ks++) {
            int row  = wm * 64 + mt * 16 + (j & 1) * 8 + r;
            int unit = ks * 2 + (j >> 1);
            a_off[mt][ks] = SWZ(row, unit);
        }
    uint32_t b_off[2][2];
    #pragma unroll
    for (int pr = 0; pr < 2; pr++)
        #pragma unroll
        for (int ks = 0; ks < 2; ks++) {
            int row  = wn * 32 + pr * 16 + (j >> 1) * 8 + r;
            int unit = ks * 2 + (j & 1);
            b_off[pr][ks] = SWZ(row, unit);
        }

    float c[4][4][4];
    #pragma unroll
    for (int mt = 0; mt < 4; mt++)
        #pragma unroll
        for (int nt = 0; nt < 4; nt++)
            #pragma unroll
            for (int q = 0; q < 4; q++) c[mt][nt][q] = 0.f;

    const int niter = K >> 4;

    auto issue = [&](int t) {
        const int s = t % STAGES;
        const uint32_t ab = as_base + s * STAGE_BYTES;
        const uint32_t bb = bs_base + s * STAGE_BYTES;
        const float* qa = pa + (size_t)t * 16;
        CP16(ab + offA0, qa,        16u);
        CP16(ab + offA1, qa + a64,  16u);
        CP16(bb + offB0, pb0 + (size_t)t * 16, bsz0);
        CP16(bb + offB1, pb1 + (size_t)t * 16, bsz1);
    };

    // prologue: fill STAGES-1 stages
    #pragma unroll
    for (int s = 0; s < STAGES - 1; ++s) {
        if (s < niter) issue(s);
        asm volatile("cp.async.commit_group;");
    }

    for (int it = 0; it < niter; ++it) {
        asm volatile("cp.async.wait_group 1;");
        __syncthreads();

        // refill the stage consumed at it-1 (safe: all warps passed the sync)
        if (it + STAGES - 1 < niter) issue(it + STAGES - 1);
        asm volatile("cp.async.commit_group;");

        const int s = it % STAGES;
        const uint32_t ab = as_base + s * STAGE_BYTES;
        const uint32_t bb = bs_base + s * STAGE_BYTES;
        #pragma unroll
        for (int ks = 0; ks < 2; ks++) {
            uint32_t bf[2][4];
            LDSM4(bf[0], bb + b_off[0][ks]);
            LDSM4(bf[1], bb + b_off[1][ks]);
            uint32_t af[4][4];
            #pragma unroll
            for (int mt = 0; mt < 4; mt++) LDSM4(af[mt], ab + a_off[mt][ks]);
            #pragma unroll
            for (int mt = 0; mt < 4; mt++)
                #pragma unroll
                for (int nt = 0; nt < 4; nt++)
                    MMA_TF32(c[mt][nt], af[mt],
                             bf[nt >> 1][(nt & 1) * 2], bf[nt >> 1][(nt & 1) * 2 + 1]);
        }
    }

    // epilogue
    #pragma unroll
    for (int mt = 0; mt < 4; mt++) {
        #pragma unroll
        for (int nt = 0; nt < 4; nt++) {
            const int m0 = bm + wm * 64 + mt * 16 + (lane >> 2);
            const int n0 = bn + wn * 32 + nt * 8 + (lane & 3) * 2;
            if (n0 >= N) continue;
            float2 v01 = make_float2(c[mt][nt][0], c[mt][nt][1]);
            float2 v23 = make_float2(c[mt][nt][2], c[mt][nt][3]);
            if (EPI == 1) {
                const float b0 = bias[n0], b1 = bias[n0 + 1];
                v01.x = softplusf(v01.x + b0); v01.y = softplusf(v01.y + b1);
                v23.x = softplusf(v23.x + b0); v23.y = softplusf(v23.y + b1);
            } else if (EPI == 2) {
                v01.x = roundtf(v01.x); v01.y = roundtf(v01.y);
                v23.x = roundtf(v23.x); v23.y = roundtf(v23.y);
            }
            *(float2*)&C[(size_t)m0 * ldc + n0]       = v01;
            *(float2*)&C[(size_t)(m0 + 8) * ldc + n0] = v23;
        }
    }
}

// ---------------- tf32 RN pre-rounding copy (vectorized) ----------------
__global__ void round_copy4(const float4* __restrict__ in, float4* __restrict__ out, int n4)
{
    int i = blockIdx.x * blockDim.x + threadIdx.x;
    if (i < n4) {
        float4 v = in[i];
        v.x = roundtf(v.x); v.y = roundtf(v.y);
        v.z = roundtf(v.z); v.w = roundtf(v.w);
        out[i] = v;
    }
}

// ---------------- depthwise causal conv (K=4) + silu, tf32-rounded out ----
#define TC 128
__global__ void conv_silu_kernel(const float* __restrict__ conv_w)
{
    const int d  = blockIdx.x * blockDim.x + threadIdx.x;
    const int t0 = blockIdx.y * TC;
    const int b  = blockIdx.z;

    const float w0 = conv_w[d*4+0], w1 = conv_w[d*4+1],
                w2 = conv_w[d*4+2], w3 = conv_w[d*4+3];

    const float* xin = g_xz + (size_t)b * L_ * XZW + d;
    float*       out = g_xconv + (size_t)b * L_ * DI + d;

    float x0 = (t0-3 >= 0) ? xin[(size_t)(t0-3)*XZW] : 0.f;
    float x1 = (t0-2 >= 0) ? xin[(size_t)(t0-2)*XZW] : 0.f;
    float x2 = (t0-1 >= 0) ? xin[(size_t)(t0-1)*XZW] : 0.f;

    for (int t = t0; t < t0 + TC; t++) {
        float x3 = xin[(size_t)t * XZW];
        float s  = fmaf(x0, w0, fmaf(x1, w1, fmaf(x2, w2, x3*w3)));
        out[(size_t)t * DI] = roundtf(siluf(s));
        x0 = x1; x1 = x2; x2 = x3;
    }
}

// ---------------- selective scan, fused skip + gate, tf32-rounded y -------
__global__ void scan_kernel(const float* __restrict__ A_log,
                            const float* __restrict__ Dp)
{
    const int gw   = (blockIdx.x * blockDim.x + threadIdx.x) >> 5;
    const int lane = threadIdx.x & 31;
    const int b    = gw >> 10;
    const int d    = ((gw & 1023) << 1) + (lane >> 4);
    const int n    = lane & 15;

    const float a  = -__expf(A_log[d*DS + n]);
    const float Dd = Dp[d];

    const float* dtr  = g_dt    + (size_t)b * L_ * DI + d;
    const float* xcr  = g_xconv + (size_t)b * L_ * DI + d;
    const float* dbb  = g_dbl   + (size_t)b * L_ * DBLW;
    const float* zr   = g_xz    + (size_t)b * L_ * XZW + DI + d;
    float*       yr   = g_y     + (size_t)b * L_ * DI + d;

    float h = 0.f;
    for (int t = 0; t < L_; t++) {
        const float dt = dtr[(size_t)t * DI];
        const float xv = xcr[(size_t)t * DI];
        const float Bn = dbb[(size_t)t * DBLW + DR + n];
        const float Cn = dbb[(size_t)t * DBLW + DR + DS + n];

        const float da = __expf(dt * a);
        h = fmaf(h, da, dt * Bn * xv);

        float p = h * Cn;
        p += __shfl_xor_sync(0xffffffffu, p, 1);
        p += __shfl_xor_sync(0xffffffffu, p, 2);
        p += __shfl_xor_sync(0xffffffffu, p, 4);
        p += __shfl_xor_sync(0xffffffffu, p, 8);

        if (n == 0) {
            const float zv = zr[(size_t)t * XZW];
            yr[(size_t)t * DI] = roundtf((p + Dd * xv) * siluf(zv));
        }
    }
}

// ---------------- launch ----------------
static inline void round_copy(const float* in, float* out, size_t n)
{
    int n4 = (int)(n / 4);
    round_copy4<<<(n4 + 255) / 256, 256>>>((const float4*)in, (float4*)out, n4);
}

extern "C" void kernel_launch(void* const* d_in, const int* in_sizes, int n_in,
                              void* d_out, int out_size)
{
    const float* x      = (const float*)d_in[0];
    const float* W_in   = (const float*)d_in[1];
    const float* conv_w = (const float*)d_in[2];
    const float* W_x    = (const float*)d_in[3];
    const float* W_dt   = (const float*)d_in[4];
    const float* b_dt   = (const float*)d_in[5];
    const float* A_log  = (const float*)d_in[6];
    const float* Dp     = (const float*)d_in[7];
    const float* W_out  = (const float*)d_in[8];
    float* out = (float*)d_out;

    float *xz, *xconv, *dbl, *dt, *y, *xr, *win, *wx, *wdt, *wout;
    cudaGetSymbolAddress((void**)&xz,    g_xz);
    cudaGetSymbolAddress((void**)&xconv, g_xconv);
    cudaGetSymbolAddress((void**)&dbl,   g_dbl);
    cudaGetSymbolAddress((void**)&dt,    g_dt);
    cudaGetSymbolAddress((void**)&y,     g_y);
    cudaGetSymbolAddress((void**)&xr,    g_xr);
    cudaGetSymbolAddress((void**)&win,   g_win);
    cudaGetSymbolAddress((void**)&wx,    g_wx);
    cudaGetSymbolAddress((void**)&wdt,   g_wdt);
    cudaGetSymbolAddress((void**)&wout,  g_wout);

    // 0) pre-round inputs to tf32 (RN)
    round_copy(x,     xr,   (size_t)ML * DM);
    round_copy(W_in,  win,  (size_t)XZW * DM);
    round_copy(W_x,   wx,   (size_t)DBLW * DI);
    round_copy(W_dt,  wdt,  (size_t)DI * DR);
    round_copy(W_out, wout, (size_t)DM * DI);

    // 1) xz = x @ W_in^T    (8192 x 4096 x 1024)
    {
        dim3 grid(XZW/128, ML/128);
        mma_nt_tf32<0><<<grid, 256>>>(ML, XZW, DM, xr, DM, win, DM, xz, XZW, nullptr);
    }
    // 2) depthwise conv + silu (rounds xconv to tf32)
    {
        dim3 grid(DI/256, L_/TC, B_);
        conv_silu_kernel<<<grid, 256>>>(conv_w);
    }
    // 3) dbl = x_conv @ W_x^T   (8192 x 96 x 2048), output rounded to tf32
    {
        dim3 grid(1, ML/128);
        mma_nt_tf32<2><<<grid, 256>>>(ML, DBLW, DI, xconv, DI, wx, DI, dbl, DBLW, nullptr);
    }
    // 4) dt = softplus(dbl[:, :64] @ W_dt^T + b_dt)   (8192 x 2048 x 64)
    {
        dim3 grid(DI/128, ML/128);
        mma_nt_tf32<1><<<grid, 256>>>(ML, DI, DR, dbl, DBLW, wdt, DR, dt, DI, b_dt);
    }
    // 5) selective scan (fused skip + gate, rounds y to tf32)
    {
        int warps = B_ * (DI/2);
        scan_kernel<<<warps*32/256, 256>>>(A_log, Dp);
    }
    // 6) out = y @ W_out^T   (8192 x 1024 x 2048)
    {
        dim3 grid(DM/128, ML/128);
        mma_nt_tf32<0><<<grid, 256>>>(ML, DM, DI, y, DI, wout, DI, out, DM, nullptr);
    }
}

// round 4
// speedup vs baseline: 1.8662x; 1.0188x over previous
#include <cuda_runtime.h>
#include <cstdint>

// ---------------- problem constants ----------------
#define B_    4
#define L_    2048
#define DM    1024          // d_model
#define DI    2048          // d_inner
#define DS    16            // d_state
#define DR    64            // dt_rank
#define XZW   (2*DI)        // 4096  width of xz
#define DBLW  (DR + 2*DS)   // 96    width of dbl
#define ML    (B_*L_)       // 8192  rows of all GEMMs

// ---------------- scratch (static device globals; allocation-free) ----------
__device__ float g_xz   [(size_t)ML * XZW];
__device__ float g_xconv[(size_t)ML * DI];
__device__ float g_dbl  [(size_t)ML * DBLW];
__device__ float g_dt   [(size_t)ML * DI];
__device__ float g_y    [(size_t)ML * DI];
// tf32-rounded copies of inputs
__device__ float g_xr   [(size_t)ML * DM];
__device__ float g_win  [(size_t)XZW * DM];
__device__ float g_wx   [(size_t)DBLW * DI];
__device__ float g_wdt  [(size_t)DI * DR];
__device__ float g_wout [(size_t)DM * DI];

// ---------------- helpers ----------------
__device__ __forceinline__ float softplusf(float x) {
    return x > 20.f ? x : log1pf(__expf(x));
}
__device__ __forceinline__ float siluf(float x) {
    return x / (1.f + __expf(-x));
}
__device__ __forceinline__ uint32_t f2tf(float f) {
    uint32_t u;
    asm("cvt.rna.tf32.f32 %0, %1;" : "=r"(u) : "f"(f));
    return u;
}
__device__ __forceinline__ float roundtf(float f) {
    return __uint_as_float(f2tf(f));
}
__device__ __forceinline__ uint32_t s2u(const void* p) {
    return (uint32_t)__cvta_generic_to_shared(p);
}

#define LDSM4(R, addr) \
    asm volatile("ldmatrix.sync.aligned.m8n8.x4.shared.b16 {%0,%1,%2,%3}, [%4];" \
        : "=r"((R)[0]), "=r"((R)[1]), "=r"((R)[2]), "=r"((R)[3]) : "r"(addr))

#define MMA_TF32(C, A, B0, B1) \
    asm volatile("mma.sync.aligned.m16n8k8.row.col.f32.tf32.tf32.f32 " \
        "{%0,%1,%2,%3}, {%4,%5,%6,%7}, {%8,%9}, {%0,%1,%2,%3};" \
        : "+f"((C)[0]), "+f"((C)[1]), "+f"((C)[2]), "+f"((C)[3]) \
        : "r"((A)[0]), "r"((A)[1]), "r"((A)[2]), "r"((A)[3]), "r"(B0), "r"(B1))

#define CP16(dst, src, sz) \
    asm volatile("cp.async.cg.shared.global [%0], [%1], 16, %2;" \
        :: "r"(dst), "l"(src), "r"(sz))

// smem unit swizzle: byte offset of float4 unit (row, kq), rows 0..127
#define SWZ(row, kq) ((((row) << 2) + ((kq) ^ (((row) >> 1) & 3))) * 16)

// ---------------- tf32 tensor-core NT GEMM, 3-stage cp.async pipeline -----
// C[M,N] = A[M,K] * B[N,K]^T.  BM=BN=128, BK=16, 128 threads,
// 2x2 warp grid, warp tile 64x64 (minimizes duplicated smem reads).
// Inputs must be pre-rounded to tf32 (RN). M%128==0, K%16==0; N guarded.
// EPI: 0=none, 1=softplus(v+bias[n]), 2=round output to tf32.
template<int EPI>
__global__ __launch_bounds__(128, 2)
void mma_nt_tf32(int M, int N, int K,
                 const float* __restrict__ A, int lda,
                 const float* __restrict__ Bm, int ldb,
                 float* __restrict__ C, int ldc,
                 const float* __restrict__ bias)
{
    constexpr int STAGES = 3;
    constexpr int STAGE_FLOATS = 128 * 16;
    constexpr int STAGE_BYTES  = STAGE_FLOATS * 4;
    __shared__ float As[STAGES * STAGE_FLOATS];
    __shared__ float Bs[STAGES * STAGE_FLOATS];

    const int tid  = threadIdx.x;
    const int lane = tid & 31;
    const int wid  = tid >> 5;        // 0..3
    const int wm   = wid & 1;         // 2 warps along M
    const int wn   = wid >> 1;        // 2 warps along N
    const int bm   = blockIdx.y * 128;
    const int bn   = blockIdx.x * 128;

    const uint32_t as_base = s2u(As);
    const uint32_t bs_base = s2u(Bs);

    // global load mapping: thread -> (rows lrow+{0,32,64,96}, kq = tid%4)
    const int lrow = tid >> 2;        // 0..31
    const int lkq  = tid & 3;
    const float* pa = A + (size_t)(bm + lrow) * lda + lkq * 4;
    const size_t a32 = (size_t)32 * lda;

    const float* pbc[4];
    uint32_t bsz[4];
    #pragma unroll
    for (int c = 0; c < 4; c++) {
        int row = bn + lrow + 32 * c;
        bsz[c] = (row < N) ? 16u : 0u;
        pbc[c] = Bm + (size_t)(row < N ? row : N - 1) * ldb + lkq * 4;
    }

    // smem store byte offsets (within a stage)
    uint32_t offS[4];
    #pragma unroll
    for (int c = 0; c < 4; c++) offS[c] = SWZ(lrow + 32 * c, lkq);

    // ldmatrix byte offsets (within a stage)
    const int r = lane & 7;
    const int j = lane >> 3;
    uint32_t a_off[4][2];    // [mtile 16-rows][kstep]
    #pragma unroll
    for (int mt = 0; mt < 4; mt++)
        #pragma unroll
        for (int ks = 0; ks < 2; ks++) {
            int row  = wm * 64 + mt * 16 + (j & 1) * 8 + r;
            int unit = ks * 2 + (j >> 1);
            a_off[mt][ks] = SWZ(row, unit);
        }
    uint32_t b_off[4][2];    // [octet-pair 16-rows][kstep]
    #pragma unroll
    for (int pr = 0; pr < 4; pr++)
        #pragma unroll
        for (int ks = 0; ks < 2; ks++) {
            int row  = wn * 64 + pr * 16 + (j >> 1) * 8 + r;
            int unit = ks * 2 + (j & 1);
            b_off[pr][ks] = SWZ(row, unit);
        }

    float c[4][8][4];
    #pragma unroll
    for (int mt = 0; mt < 4; mt++)
        #pragma unroll
        for (int nt = 0; nt < 8; nt++)
            #pragma unroll
            for (int q = 0; q < 4; q++) c[mt][nt][q] = 0.f;

    const int niter = K >> 4;

    auto issue = [&](int t) {
        const int s = t % STAGES;
        const uint32_t ab = as_base + s * STAGE_BYTES;
        const uint32_t bb = bs_base + s * STAGE_BYTES;
        const float* qa = pa + (size_t)t * 16;
        #pragma unroll
        for (int ch = 0; ch < 4; ch++)
            CP16(ab + offS[ch], qa + ch * a32, 16u);
        #pragma unroll
        for (int ch = 0; ch < 4; ch++)
            CP16(bb + offS[ch], pbc[ch] + (size_t)t * 16, bsz[ch]);
    };

    #pragma unroll
    for (int s = 0; s < STAGES - 1; ++s) {
        if (s < niter) issue(s);
        asm volatile("cp.async.commit_group;");
    }

    for (int it = 0; it < niter; ++it) {
        asm volatile("cp.async.wait_group 1;");
        __syncthreads();

        if (it + STAGES - 1 < niter) issue(it + STAGES - 1);
        asm volatile("cp.async.commit_group;");

        const int s = it % STAGES;
        const uint32_t ab = as_base + s * STAGE_BYTES;
        const uint32_t bb = bs_base + s * STAGE_BYTES;
        #pragma unroll
        for (int ks = 0; ks < 2; ks++) {
            uint32_t bf[4][4];
            #pragma unroll
            for (int pr = 0; pr < 4; pr++) LDSM4(bf[pr], bb + b_off[pr][ks]);
            uint32_t af[4][4];
            #pragma unroll
            for (int mt = 0; mt < 4; mt++) LDSM4(af[mt], ab + a_off[mt][ks]);
            #pragma unroll
            for (int mt = 0; mt < 4; mt++)
                #pragma unroll
                for (int nt = 0; nt < 8; nt++)
                    MMA_TF32(c[mt][nt], af[mt],
                             bf[nt >> 1][(nt & 1) * 2], bf[nt >> 1][(nt & 1) * 2 + 1]);
        }
    }

    // epilogue
    #pragma unroll
    for (int mt = 0; mt < 4; mt++) {
        #pragma unroll
        for (int nt = 0; nt < 8; nt++) {
            const int m0 = bm + wm * 64 + mt * 16 + (lane >> 2);
            const int n0 = bn + wn * 64 + nt * 8 + (lane & 3) * 2;
            if (n0 >= N) continue;
            float2 v01 = make_float2(c[mt][nt][0], c[mt][nt][1]);
            float2 v23 = make_float2(c[mt][nt][2], c[mt][nt][3]);
            if (EPI == 1) {
                const float b0 = bias[n0], b1 = bias[n0 + 1];
                v01.x = softplusf(v01.x + b0); v01.y = softplusf(v01.y + b1);
                v23.x = softplusf(v23.x + b0); v23.y = softplusf(v23.y + b1);
            } else if (EPI == 2) {
                v01.x = roundtf(v01.x); v01.y = roundtf(v01.y);
                v23.x = roundtf(v23.x); v23.y = roundtf(v23.y);
            }
            *(float2*)&C[(size_t)m0 * ldc + n0]       = v01;
            *(float2*)&C[(size_t)(m0 + 8) * ldc + n0] = v23;
        }
    }
}

// ---------------- tf32 RN pre-rounding copy (vectorized) ----------------
__global__ void round_copy4(const float4* __restrict__ in, float4* __restrict__ out, int n4)
{
    int i = blockIdx.x * blockDim.x + threadIdx.x;
    if (i < n4) {
        float4 v = in[i];
        v.x = roundtf(v.x); v.y = roundtf(v.y);
        v.z = roundtf(v.z); v.w = roundtf(v.w);
        out[i] = v;
    }
}

// ---------------- depthwise causal conv (K=4) + silu, tf32-rounded out ----
#define TC 128
__global__ void conv_silu_kernel(const float* __restrict__ conv_w)
{
    const int d  = blockIdx.x * blockDim.x + threadIdx.x;
    const int t0 = blockIdx.y * TC;
    const int b  = blockIdx.z;

    const float w0 = conv_w[d*4+0], w1 = conv_w[d*4+1],
                w2 = conv_w[d*4+2], w3 = conv_w[d*4+3];

    const float* xin = g_xz + (size_t)b * L_ * XZW + d;
    float*       out = g_xconv + (size_t)b * L_ * DI + d;

    float x0 = (t0-3 >= 0) ? xin[(size_t)(t0-3)*XZW] : 0.f;
    float x1 = (t0-2 >= 0) ? xin[(size_t)(t0-2)*XZW] : 0.f;
    float x2 = (t0-1 >= 0) ? xin[(size_t)(t0-1)*XZW] : 0.f;

    for (int t = t0; t < t0 + TC; t++) {
        float x3 = xin[(size_t)t * XZW];
        float s  = fmaf(x0, w0, fmaf(x1, w1, fmaf(x2, w2, x3*w3)));
        out[(size_t)t * DI] = roundtf(siluf(s));
        x0 = x1; x1 = x2; x2 = x3;
    }
}

// ---------------- selective scan, fused skip + gate, tf32-rounded y -------
__global__ void scan_kernel(const float* __restrict__ A_log,
                            const float* __restrict__ Dp)
{
    const int gw   = (blockIdx.x * blockDim.x + threadIdx.x) >> 5;
    const int lane = threadIdx.x & 31;
    const int b    = gw >> 10;
    const int d    = ((gw & 1023) << 1) + (lane >> 4);
    const int n    = lane & 15;

    const float a  = -__expf(A_log[d*DS + n]);
    const float Dd = Dp[d];

    const float* dtr  = g_dt    + (size_t)b * L_ * DI + d;
    const float* xcr  = g_xconv + (size_t)b * L_ * DI + d;
    const float* dbb  = g_dbl   + (size_t)b * L_ * DBLW;
    const float* zr   = g_xz    + (size_t)b * L_ * XZW + DI + d;
    float*       yr   = g_y     + (size_t)b * L_ * DI + d;

    float h = 0.f;
    for (int t = 0; t < L_; t++) {
        const float dt = dtr[(size_t)t * DI];
        const float xv = xcr[(size_t)t * DI];
        const float Bn = dbb[(size_t)t * DBLW + DR + n];
        const float Cn = dbb[(size_t)t * DBLW + DR + DS + n];

        const float da = __expf(dt * a);
        h = fmaf(h, da, dt * Bn * xv);

        float p = h * Cn;
        p += __shfl_xor_sync(0xffffffffu, p, 1);
        p += __shfl_xor_sync(0xffffffffu, p, 2);
        p += __shfl_xor_sync(0xffffffffu, p, 4);
        p += __shfl_xor_sync(0xffffffffu, p, 8);

        if (n == 0) {
            const float zv = zr[(size_t)t * XZW];
            yr[(size_t)t * DI] = roundtf((p + Dd * xv) * siluf(zv));
        }
    }
}

// ---------------- launch ----------------
static inline void round_copy(const float* in, float* out, size_t n)
{
    int n4 = (int)(n / 4);
    round_copy4<<<(n4 + 255) / 256, 256>>>((const float4*)in, (float4*)out, n4);
}

extern "C" void kernel_launch(void* const* d_in, const int* in_sizes, int n_in,
                              void* d_out, int out_size)
{
    const float* x      = (const float*)d_in[0];
    const float* W_in   = (const float*)d_in[1];
    const float* conv_w = (const float*)d_in[2];
    const float* W_x    = (const float*)d_in[3];
    const float* W_dt   = (const float*)d_in[4];
    const float* b_dt   = (const float*)d_in[5];
    const float* A_log  = (const float*)d_in[6];
    const float* Dp     = (const float*)d_in[7];
    const float* W_out  = (const float*)d_in[8];
    float* out = (float*)d_out;

    float *xz, *xconv, *dbl, *dt, *y, *xr, *win, *wx, *wdt, *wout;
    cudaGetSymbolAddress((void**)&xz,    g_xz);
    cudaGetSymbolAddress((void**)&xconv, g_xconv);
    cudaGetSymbolAddress((void**)&dbl,   g_dbl);
    cudaGetSymbolAddress((void**)&dt,    g_dt);
    cudaGetSymbolAddress((void**)&y,     g_y);
    cudaGetSymbolAddress((void**)&xr,    g_xr);
    cudaGetSymbolAddress((void**)&win,   g_win);
    cudaGetSymbolAddress((void**)&wx,    g_wx);
    cudaGetSymbolAddress((void**)&wdt,   g_wdt);
    cudaGetSymbolAddress((void**)&wout,  g_wout);

    // 0) pre-round inputs to tf32 (RN)
    round_copy(x,     xr,   (size_t)ML * DM);
    round_copy(W_in,  win,  (size_t)XZW * DM);
    round_copy(W_x,   wx,   (size_t)DBLW * DI);
    round_copy(W_dt,  wdt,  (size_t)DI * DR);
    round_copy(W_out, wout, (size_t)DM * DI);

    // 1) xz = x @ W_in^T    (8192 x 4096 x 1024)
    {
        dim3 grid(XZW/128, ML/128);
        mma_nt_tf32<0><<<grid, 128>>>(ML, XZW, DM, xr, DM, win, DM, xz, XZW, nullptr);
    }
    // 2) depthwise conv + silu (rounds xconv to tf32)
    {
        dim3 grid(DI/256, L_/TC, B_);
        conv_silu_kernel<<<grid, 256>>>(conv_w);
    }
    // 3) dbl = x_conv @ W_x^T   (8192 x 96 x 2048), output rounded to tf32
    {
        dim3 grid(1, ML/128);
        mma_nt_tf32<2><<<grid, 128>>>(ML, DBLW, DI, xconv, DI, wx, DI, dbl, DBLW, nullptr);
    }
    // 4) dt = softplus(dbl[:, :64] @ W_dt^T + b_dt)   (8192 x 2048 x 64)
    {
        dim3 grid(DI/128, ML/128);
        mma_nt_tf32<1><<<grid, 128>>>(ML, DI, DR, dbl, DBLW, wdt, DR, dt, DI, b_dt);
    }
    // 5) selective scan (fused skip + gate, rounds y to tf32)
    {
        int warps = B_ * (DI/2);
        scan_kernel<<<warps*32/256, 256>>>(A_log, Dp);
    }
    // 6) out = y @ W_out^T   (8192 x 1024 x 2048)
    {
        dim3 grid(DM/128, ML/128);
        mma_nt_tf32<0><<<grid, 128>>>(ML, DM, DI, y, DI, wout, DI, out, DM, nullptr);
    }
}